// round 13
// baseline (speedup 1.0000x reference)
#include <cuda_runtime.h>
#include <cuda_fp16.h>
#include <cstdint>

// ---------------------------------------------------------------------------
// NNUE: out[b] = tanh(relu(relu((sum_f emb[idx[f,b]]) @ w1^T + b1) @ w2^T + b2) @ w3^T + b3)
//
// K1: g_tbl = emb @ w1^T ([49152,32]) via mma.sync.m16n8k16 FP16 single-term,
//     64 rows/CTA (grid 768: balanced waves, more concurrent LDG streams).
// K2: 32-feature gather (64B fp16 rows) + tiny MLP; gathers batched 4-wide
//     in registers for real memory-level parallelism.
// ---------------------------------------------------------------------------

#define FULLMASK 0xffffffffu

constexpr int INPUT_DIM = 49152;
constexpr int EMB_DIM   = 256;
constexpr int BATCH     = 16384;

__device__ __half g_tbl[INPUT_DIM * 32];

__device__ __forceinline__ uint32_t smem_u32(const void* p) {
    uint32_t a;
    asm("{ .reg .u64 t; cvta.to.shared.u64 t, %1; cvt.u32.u64 %0, t; }" : "=r"(a) : "l"(p));
    return a;
}
__device__ __forceinline__ void ldmat_x4(uint32_t r[4], uint32_t addr) {
    asm volatile("ldmatrix.sync.aligned.m8n8.x4.shared.b16 {%0,%1,%2,%3}, [%4];"
                 : "=r"(r[0]), "=r"(r[1]), "=r"(r[2]), "=r"(r[3]) : "r"(addr));
}
__device__ __forceinline__ void mma_f16(float d[4], const uint32_t a[4],
                                        uint32_t b0, uint32_t b1) {
    asm volatile("mma.sync.aligned.m16n8k16.row.col.f32.f16.f16.f32 "
                 "{%0,%1,%2,%3}, {%4,%5,%6,%7}, {%8,%9}, {%0,%1,%2,%3};"
                 : "+f"(d[0]), "+f"(d[1]), "+f"(d[2]), "+f"(d[3])
                 : "r"(a[0]), "r"(a[1]), "r"(a[2]), "r"(a[3]), "r"(b0), "r"(b1));
}
__device__ __forceinline__ uint32_t cvt2h(float x, float y) {
    __half2 h = __float22half2_rn(make_float2(x, y));
    return *(uint32_t*)&h;
}

// ---------------------------------------------------------------------------
// Kernel 1.  CTA: 128 threads = 4 warps; 64 rows (one m16 tile per warp);
// grid 768. K in 8 chunks of 32; A double-buffered; B resident.
// Dynamic smem: 2 x 5120 + 16896 = 27136 B.
// ---------------------------------------------------------------------------
constexpr int A_STRIDE = 80;    // bytes per A row: 32 fp16 = 64 + 16 pad
constexpr int B_STRIDE = 528;   // bytes per B row: 256 fp16 = 512 + 16 pad
constexpr int SZ_A = 64 * A_STRIDE;                   // 5120
constexpr int SZ_B = 32 * B_STRIDE;                   // 16896
constexpr int K1_SMEM = 2 * SZ_A + SZ_B;              // 27136

__global__ __launch_bounds__(128)
void k1_precompute(const float* __restrict__ emb, const float* __restrict__ w1) {
    extern __shared__ __align__(16) char dsm[];
    char* sA0 = dsm;
    char* sA1 = dsm + SZ_A;
    char* sB  = dsm + 2 * SZ_A;

    const int tid  = threadIdx.x;
    const int wid  = tid >> 5;
    const int lane = tid & 31;
    const int rowBase = blockIdx.x * 64;

    // ---- Prologue: convert w1 (32x256) to fp16 ----
    {
        const float4* src = (const float4*)w1;
        for (int i = tid; i < 2048; i += 128) {
            const float4 v = src[i];
            const int n = i >> 6;
            const int k = (i & 63) * 4;
            *(uint2*)(sB + n * B_STRIDE + k * 2) =
                make_uint2(cvt2h(v.x, v.y), cvt2h(v.z, v.w));
        }
    }

    const int gRow = tid >> 3;          // 0..15
    const int gSeg = tid & 7;           // float4 seg of the 32-k window

    // ---- Stage chunk 0 into buffer 0 (rows p*16+gRow, p=0..3) ----
#pragma unroll
    for (int p = 0; p < 4; p++) {
        const int row = p * 16 + gRow;
        const float4 v = *(const float4*)&emb[(size_t)(rowBase + row) * EMB_DIM + gSeg * 4];
        *(uint2*)(sA0 + row * A_STRIDE + gSeg * 8) =
            make_uint2(cvt2h(v.x, v.y), cvt2h(v.z, v.w));
    }
    __syncthreads();

    const uint32_t aOff = (uint32_t)((wid * 16 + (lane & 15)) * A_STRIDE + (lane >> 4) * 16);
    const int bN0 = (lane & 7) + ((lane >> 4) & 1) * 8;
    const uint32_t bKoff = (uint32_t)(((lane >> 3) & 1) * 16);
    const uint32_t bBase0 = smem_u32(sB) + (uint32_t)(bN0 * B_STRIDE) + bKoff;
    const uint32_t bBase1 = bBase0 + 16 * B_STRIDE;
    const uint32_t aB0 = smem_u32(sA0) + aOff;
    const uint32_t aB1 = smem_u32(sA1) + aOff;

    float d[4][4];
#pragma unroll
    for (int nt = 0; nt < 4; nt++)
#pragma unroll
        for (int r = 0; r < 4; r++) d[nt][r] = 0.0f;

#pragma unroll 1
    for (int c = 0; c < 8; ++c) {
        const uint32_t aBase = (c & 1) ? aB1 : aB0;

        float4 pre[4];
        if (c < 7) {
#pragma unroll
            for (int p = 0; p < 4; p++)
                pre[p] = *(const float4*)&emb[(size_t)(rowBase + p * 16 + gRow) * EMB_DIM
                                              + (c + 1) * 32 + gSeg * 4];
        }

#pragma unroll
        for (int ks = 0; ks < 2; ++ks) {
            const uint32_t ak = (uint32_t)(ks * 32);
            const uint32_t bk = (uint32_t)(c * 64 + ks * 32);
            uint32_t aH[4];
            ldmat_x4(aH, aBase + ak);
            uint32_t b01[4], b23[4];
            ldmat_x4(b01, bBase0 + bk);
            ldmat_x4(b23, bBase1 + bk);

            mma_f16(d[0], aH, b01[0], b01[1]);
            mma_f16(d[1], aH, b01[2], b01[3]);
            mma_f16(d[2], aH, b23[0], b23[1]);
            mma_f16(d[3], aH, b23[2], b23[3]);
        }

        if (c < 7) {
            char* dst = (c & 1) ? sA0 : sA1;
#pragma unroll
            for (int p = 0; p < 4; p++) {
                const int row = p * 16 + gRow;
                *(uint2*)(dst + row * A_STRIDE + gSeg * 8) =
                    make_uint2(cvt2h(pre[p].x, pre[p].y), cvt2h(pre[p].z, pre[p].w));
            }
            __syncthreads();
        }
    }

    // ---- Epilogue: D fragments -> fp16 g_tbl ----
    const int g = lane >> 2;
    const int cp = (lane & 3) * 2;
    const int r0 = rowBase + wid * 16 + g;
#pragma unroll
    for (int nt = 0; nt < 4; nt++) {
        const int col = nt * 8 + cp;
        *(__half2*)&g_tbl[(size_t)r0 * 32 + col] =
            __float22half2_rn(make_float2(d[nt][0], d[nt][1]));
        *(__half2*)&g_tbl[(size_t)(r0 + 8) * 32 + col] =
            __float22half2_rn(make_float2(d[nt][2], d[nt][3]));
    }
}

// ---------------------------------------------------------------------------
// Kernel 2: 16 elems/block, 256 threads, grid 1024.
// Phase 1: thread = (elem, feature-quarter q, 16B-seg s): sums 8 fp16 rows'
//   segment in fp32. Gathers batched as two 4-wide register groups so 4-8
//   independent LDG.128 are in flight per thread.
// Phase 2: warp per 2 elems: h1 from smem partials, shfl MLP.
// ---------------------------------------------------------------------------
__global__ __launch_bounds__(256)
void k2_forward(const int* __restrict__ indices,
                const float* __restrict__ b1,
                const float* __restrict__ w2,
                const float* __restrict__ b2,
                const float* __restrict__ w3,
                const float* __restrict__ b3,
                float* __restrict__ out) {
    __shared__ __align__(16) float w2s[32 * 36];
    __shared__ float w3s[32];
    __shared__ int   idx_s[16][33];
    __shared__ __align__(16) float part[4][16][32];

    const int tid = threadIdx.x;
    const int b0 = blockIdx.x * 16;

    for (int t = tid; t < 1024; t += 256)
        w2s[(t >> 5) * 36 + (t & 31)] = w2[t];
    if (tid < 32) w3s[tid] = w3[tid];
    for (int t = tid; t < 512; t += 256) {
        const int f = t >> 4, e = t & 15;
        idx_s[e][f] = indices[f * BATCH + b0 + e];     // coalesced 64B runs
    }
    __syncthreads();

    // ---- Phase 1: gather-accumulate, 4-wide load batches ----
    {
        const int e = tid >> 4;             // 0..15
        const int q = (tid >> 2) & 3;       // feature quarter (8 feats)
        const int s = tid & 3;              // 16B segment
        const int* idxp = &idx_s[e][q * 8];
        const char* gt = (const char*)g_tbl;

        float acc[8];
#pragma unroll
        for (int j = 0; j < 8; j++) acc[j] = 0.0f;

#pragma unroll
        for (int grp = 0; grp < 2; ++grp) {
            uint4 v[4];
#pragma unroll
            for (int i = 0; i < 4; ++i)
                v[i] = *(const uint4*)(gt + ((size_t)idxp[grp * 4 + i] << 6) + s * 16);
#pragma unroll
            for (int i = 0; i < 4; ++i) {
                const __half2* hp = (const __half2*)&v[i];
#pragma unroll
                for (int j = 0; j < 4; j++) {
                    const float2 f2 = __half22float2(hp[j]);
                    acc[2 * j]     += f2.x;
                    acc[2 * j + 1] += f2.y;
                }
            }
        }
        float* dst = &part[q][e][s * 8];
        *(float4*)(dst)     = make_float4(acc[0], acc[1], acc[2], acc[3]);
        *(float4*)(dst + 4) = make_float4(acc[4], acc[5], acc[6], acc[7]);
    }
    __syncthreads();

    // ---- Phase 2: MLP, warp per 2 elems ----
    const int lane = tid & 31;
    const int e0 = (tid >> 5) * 2;

    float4 wrow[8];
#pragma unroll
    for (int i = 0; i < 8; i++)
        wrow[i] = *(const float4*)&w2s[lane * 36 + i * 4];
    const float* wr = (const float*)wrow;

    const float bb1 = b1[lane];
    const float h1a = fmaxf(bb1 + (part[0][e0][lane] + part[1][e0][lane])
                                + (part[2][e0][lane] + part[3][e0][lane]), 0.0f);
    const float h1b = fmaxf(bb1 + (part[0][e0 + 1][lane] + part[1][e0 + 1][lane])
                                + (part[2][e0 + 1][lane] + part[3][e0 + 1][lane]), 0.0f);

    float h2a = b2[lane], h2b = h2a;
#pragma unroll
    for (int k = 0; k < 32; ++k) {
        const float va = __shfl_sync(FULLMASK, h1a, k);
        const float vb = __shfl_sync(FULLMASK, h1b, k);
        h2a = fmaf(va, wr[k], h2a);
        h2b = fmaf(vb, wr[k], h2b);
    }
    h2a = fmaxf(h2a, 0.0f);
    h2b = fmaxf(h2b, 0.0f);

    float pa = h2a * w3s[lane];
    float pb = h2b * w3s[lane];
#pragma unroll
    for (int off = 16; off; off >>= 1) {
        pa += __shfl_xor_sync(FULLMASK, pa, off);
        pb += __shfl_xor_sync(FULLMASK, pb, off);
    }

    const float r = (lane & 1) ? pb : pa;
    if (lane < 2)
        out[b0 + e0 + lane] = tanhf(r + b3[0]);
}

// ---------------------------------------------------------------------------
extern "C" void kernel_launch(void* const* d_in, const int* in_sizes, int n_in,
                              void* d_out, int out_size) {
    const int*   indices = (const int*)  d_in[0];
    const float* emb     = (const float*)d_in[1];
    const float* w1      = (const float*)d_in[2];
    const float* b1      = (const float*)d_in[3];
    const float* w2      = (const float*)d_in[4];
    const float* b2      = (const float*)d_in[5];
    const float* w3      = (const float*)d_in[6];
    const float* b3      = (const float*)d_in[7];
    float* out = (float*)d_out;

    static bool attr_set = false;
    if (!attr_set) {
        cudaFuncSetAttribute(k1_precompute,
                             cudaFuncAttributeMaxDynamicSharedMemorySize, K1_SMEM);
        attr_set = true;
    }

    k1_precompute<<<INPUT_DIM / 64, 128, K1_SMEM>>>(emb, w1);          // 768 blocks
    k2_forward<<<BATCH / 16, 256>>>(indices, b1, w2, b2, w3, b3, out); // 1024 blocks
}

// round 14
// speedup vs baseline: 1.0903x; 1.0903x over previous
#include <cuda_runtime.h>
#include <cuda_fp16.h>
#include <cstdint>

// ---------------------------------------------------------------------------
// NNUE: out[b] = tanh(relu(relu((sum_f emb[idx[f,b]]) @ w1^T + b1) @ w2^T + b2) @ w3^T + b3)
//
// K1 (R12, best measured): g_tbl = emb @ w1^T via mma.sync m16n8k16 fp16
//     single-term, 128 rows/CTA, A double-buffered, B resident. g_tbl fp16.
// K2 (new): warp-coalesced gather. One LDG.32 covers TWO 64B fp16 rows
//     (lanes 0-15 row 2p, lanes 16-31 row 2p+1) -> 16 LDG/elem = 262K total
//     (was 2.1M; K2 was LDG-issue-floor bound). shfl_xor(16) merges halves.
// ---------------------------------------------------------------------------

#define FULLMASK 0xffffffffu

constexpr int INPUT_DIM = 49152;
constexpr int EMB_DIM   = 256;
constexpr int BATCH     = 16384;

__device__ __half g_tbl[INPUT_DIM * 32];

__device__ __forceinline__ uint32_t smem_u32(const void* p) {
    uint32_t a;
    asm("{ .reg .u64 t; cvta.to.shared.u64 t, %1; cvt.u32.u64 %0, t; }" : "=r"(a) : "l"(p));
    return a;
}
__device__ __forceinline__ void ldmat_x4(uint32_t r[4], uint32_t addr) {
    asm volatile("ldmatrix.sync.aligned.m8n8.x4.shared.b16 {%0,%1,%2,%3}, [%4];"
                 : "=r"(r[0]), "=r"(r[1]), "=r"(r[2]), "=r"(r[3]) : "r"(addr));
}
__device__ __forceinline__ void mma_f16(float d[4], const uint32_t a[4],
                                        uint32_t b0, uint32_t b1) {
    asm volatile("mma.sync.aligned.m16n8k16.row.col.f32.f16.f16.f32 "
                 "{%0,%1,%2,%3}, {%4,%5,%6,%7}, {%8,%9}, {%0,%1,%2,%3};"
                 : "+f"(d[0]), "+f"(d[1]), "+f"(d[2]), "+f"(d[3])
                 : "r"(a[0]), "r"(a[1]), "r"(a[2]), "r"(a[3]), "r"(b0), "r"(b1));
}
__device__ __forceinline__ uint32_t cvt2h(float x, float y) {
    __half2 h = __float22half2_rn(make_float2(x, y));
    return *(uint32_t*)&h;
}

// ---------------------------------------------------------------------------
// Kernel 1 (R12 verbatim).  CTA: 128 threads = 4 warps; 128 rows; grid 384.
// ---------------------------------------------------------------------------
constexpr int A_STRIDE = 80;
constexpr int B_STRIDE = 528;
constexpr int SZ_A = 128 * A_STRIDE;                  // 10240
constexpr int SZ_B = 32 * B_STRIDE;                   // 16896
constexpr int K1_SMEM = 2 * SZ_A + SZ_B;              // 37376

__global__ __launch_bounds__(128)
void k1_precompute(const float* __restrict__ emb, const float* __restrict__ w1) {
    extern __shared__ __align__(16) char dsm[];
    char* sA0 = dsm;
    char* sA1 = dsm + SZ_A;
    char* sB  = dsm + 2 * SZ_A;

    const int tid  = threadIdx.x;
    const int wid  = tid >> 5;
    const int lane = tid & 31;
    const int rowBase = blockIdx.x * 128;

    {
        const float4* src = (const float4*)w1;
        for (int i = tid; i < 2048; i += 128) {
            const float4 v = src[i];
            const int n = i >> 6;
            const int k = (i & 63) * 4;
            *(uint2*)(sB + n * B_STRIDE + k * 2) =
                make_uint2(cvt2h(v.x, v.y), cvt2h(v.z, v.w));
        }
    }

    const int gRow = tid >> 3;
    const int gSeg = tid & 7;

#pragma unroll
    for (int p = 0; p < 8; p++) {
        const int row = p * 16 + gRow;
        const float4 v = *(const float4*)&emb[(size_t)(rowBase + row) * EMB_DIM + gSeg * 4];
        *(uint2*)(sA0 + row * A_STRIDE + gSeg * 8) =
            make_uint2(cvt2h(v.x, v.y), cvt2h(v.z, v.w));
    }
    __syncthreads();

    const uint32_t aOff = (uint32_t)((wid * 32 + (lane & 15)) * A_STRIDE + (lane >> 4) * 16);
    const int bN0 = (lane & 7) + ((lane >> 4) & 1) * 8;
    const uint32_t bKoff = (uint32_t)(((lane >> 3) & 1) * 16);
    const uint32_t bBase0 = smem_u32(sB) + (uint32_t)(bN0 * B_STRIDE) + bKoff;
    const uint32_t bBase1 = bBase0 + 16 * B_STRIDE;
    const uint32_t aB0 = smem_u32(sA0) + aOff;
    const uint32_t aB1 = smem_u32(sA1) + aOff;

    float d[2][4][4];
#pragma unroll
    for (int mt = 0; mt < 2; mt++)
#pragma unroll
        for (int nt = 0; nt < 4; nt++)
#pragma unroll
            for (int r = 0; r < 4; r++) d[mt][nt][r] = 0.0f;

#pragma unroll 1
    for (int c = 0; c < 8; ++c) {
        const uint32_t aBase = (c & 1) ? aB1 : aB0;

        float4 pre[8];
        if (c < 7) {
#pragma unroll
            for (int p = 0; p < 8; p++)
                pre[p] = *(const float4*)&emb[(size_t)(rowBase + p * 16 + gRow) * EMB_DIM
                                              + (c + 1) * 32 + gSeg * 4];
        }

#pragma unroll
        for (int ks = 0; ks < 2; ++ks) {
            const uint32_t ak = (uint32_t)(ks * 32);
            const uint32_t bk = (uint32_t)(c * 64 + ks * 32);
            uint32_t aH[2][4];
            ldmat_x4(aH[0], aBase + ak);
            ldmat_x4(aH[1], aBase + ak + 16 * A_STRIDE);
            uint32_t b01[4], b23[4];
            ldmat_x4(b01, bBase0 + bk);
            ldmat_x4(b23, bBase1 + bk);

#pragma unroll
            for (int mt = 0; mt < 2; mt++) {
                mma_f16(d[mt][0], aH[mt], b01[0], b01[1]);
                mma_f16(d[mt][1], aH[mt], b01[2], b01[3]);
                mma_f16(d[mt][2], aH[mt], b23[0], b23[1]);
                mma_f16(d[mt][3], aH[mt], b23[2], b23[3]);
            }
        }

        if (c < 7) {
            char* dst = (c & 1) ? sA0 : sA1;
#pragma unroll
            for (int p = 0; p < 8; p++) {
                const int row = p * 16 + gRow;
                *(uint2*)(dst + row * A_STRIDE + gSeg * 8) =
                    make_uint2(cvt2h(pre[p].x, pre[p].y), cvt2h(pre[p].z, pre[p].w));
            }
            __syncthreads();
        }
    }

    const int g = lane >> 2;
    const int cp = (lane & 3) * 2;
#pragma unroll
    for (int mt = 0; mt < 2; mt++) {
        const int r0 = rowBase + wid * 32 + mt * 16 + g;
#pragma unroll
        for (int nt = 0; nt < 4; nt++) {
            const int col = nt * 8 + cp;
            *(__half2*)&g_tbl[(size_t)r0 * 32 + col] =
                __float22half2_rn(make_float2(d[mt][nt][0], d[mt][nt][1]));
            *(__half2*)&g_tbl[(size_t)(r0 + 8) * 32 + col] =
                __float22half2_rn(make_float2(d[mt][nt][2], d[mt][nt][3]));
        }
    }
}

// ---------------------------------------------------------------------------
// Kernel 2: 16 elems/block, 256 threads = 8 warps, grid 1024.
// Warp handles 2 elems end-to-end (no smem partials):
//  Gather: pair p (16 per elem): lanes 0-15 read row idx[2p], lanes 16-31
//    row idx[2p+1]; lane loads one half2 (cols 2*l16, 2*l16+1). One LDG.32
//    per 2 rows. acc merged across halves via shfl_xor(16).
//  h1 lives as float2-per-lane (lanes 0-15 authoritative, duplicated above).
//  Layer2: h2[lane] += shfl(h1pair, kp).x*w2[lane][2kp] + .y*w2[lane][2kp+1].
//  Layer3: warp reduce, tanh, 2 writes.
// ---------------------------------------------------------------------------
__global__ __launch_bounds__(256)
void k2_forward(const int* __restrict__ indices,
                const float* __restrict__ b1,
                const float* __restrict__ w2,
                const float* __restrict__ b2,
                const float* __restrict__ w3,
                const float* __restrict__ b3,
                float* __restrict__ out) {
    __shared__ __align__(8) float w2s[32 * 34];   // stride 34 (8B-aligned pairs)
    __shared__ float w3s[32];
    __shared__ float b1s[32];
    __shared__ int   idx_s[16][33];

    const int tid = threadIdx.x;
    const int b0 = blockIdx.x * 16;

    for (int t = tid; t < 1024; t += 256)
        w2s[(t >> 5) * 34 + (t & 31)] = w2[t];
    if (tid < 32) { w3s[tid] = w3[tid]; b1s[tid] = b1[tid]; }
    for (int t = tid; t < 512; t += 256) {
        const int f = t >> 4, e = t & 15;
        idx_s[e][f] = indices[f * BATCH + b0 + e];     // coalesced 64B runs
    }
    __syncthreads();

    const int lane = tid & 31;
    const int half = lane >> 4;          // 0: even-index rows, 1: odd
    const int l16  = lane & 15;          // col pair 2*l16, 2*l16+1
    const int e0 = (tid >> 5) * 2;

    const char* gt = (const char*)g_tbl;
    const uint32_t colOff = (uint32_t)(l16 * 4);   // byte offset within 64B row

    // ---- Gather both elems, interleaved (32 independent LDG.32 chains) ----
    float2 accA = make_float2(0.f, 0.f);
    float2 accB = make_float2(0.f, 0.f);
    const int* ia = idx_s[e0];
    const int* ib = idx_s[e0 + 1];
#pragma unroll
    for (int p = 0; p < 16; ++p) {
        const int idA = ia[2 * p + half];            // 2-addr broadcast LDS
        const int idB = ib[2 * p + half];
        const __half2 va = *(const __half2*)(gt + ((size_t)idA << 6) + colOff);
        const __half2 vb = *(const __half2*)(gt + ((size_t)idB << 6) + colOff);
        const float2 fa = __half22float2(va);
        const float2 fb = __half22float2(vb);
        accA.x += fa.x; accA.y += fa.y;
        accB.x += fb.x; accB.y += fb.y;
    }
    // Merge even/odd-feature halves (lane j <-> j^16 hold same col pair).
    accA.x += __shfl_xor_sync(FULLMASK, accA.x, 16);
    accA.y += __shfl_xor_sync(FULLMASK, accA.y, 16);
    accB.x += __shfl_xor_sync(FULLMASK, accB.x, 16);
    accB.y += __shfl_xor_sync(FULLMASK, accB.y, 16);

    const float2 b1p = make_float2(b1s[2 * l16], b1s[2 * l16 + 1]);
    float2 h1a = make_float2(fmaxf(accA.x + b1p.x, 0.f), fmaxf(accA.y + b1p.y, 0.f));
    float2 h1b = make_float2(fmaxf(accB.x + b1p.x, 0.f), fmaxf(accB.y + b1p.y, 0.f));

    // ---- Layer 2: h2[lane] over 16 shfl'd col-pairs ----
    float h2a = b2[lane], h2b = h2a;
    const float* wrow = &w2s[lane * 34];
#pragma unroll
    for (int kp = 0; kp < 16; ++kp) {
        const float wx = wrow[2 * kp];
        const float wy = wrow[2 * kp + 1];
        const float ax = __shfl_sync(FULLMASK, h1a.x, kp);
        const float ay = __shfl_sync(FULLMASK, h1a.y, kp);
        const float bx = __shfl_sync(FULLMASK, h1b.x, kp);
        const float by = __shfl_sync(FULLMASK, h1b.y, kp);
        h2a = fmaf(ax, wx, h2a); h2a = fmaf(ay, wy, h2a);
        h2b = fmaf(bx, wx, h2b); h2b = fmaf(by, wy, h2b);
    }
    h2a = fmaxf(h2a, 0.0f);
    h2b = fmaxf(h2b, 0.0f);

    // ---- Layer 3 ----
    float pa = h2a * w3s[lane];
    float pb = h2b * w3s[lane];
#pragma unroll
    for (int off = 16; off; off >>= 1) {
        pa += __shfl_xor_sync(FULLMASK, pa, off);
        pb += __shfl_xor_sync(FULLMASK, pb, off);
    }

    const float r = (lane & 1) ? pb : pa;
    if (lane < 2)
        out[b0 + e0 + lane] = tanhf(r + b3[0]);
}

// ---------------------------------------------------------------------------
extern "C" void kernel_launch(void* const* d_in, const int* in_sizes, int n_in,
                              void* d_out, int out_size) {
    const int*   indices = (const int*)  d_in[0];
    const float* emb     = (const float*)d_in[1];
    const float* w1      = (const float*)d_in[2];
    const float* b1      = (const float*)d_in[3];
    const float* w2      = (const float*)d_in[4];
    const float* b2      = (const float*)d_in[5];
    const float* w3      = (const float*)d_in[6];
    const float* b3      = (const float*)d_in[7];
    float* out = (float*)d_out;

    static bool attr_set = false;
    if (!attr_set) {
        cudaFuncSetAttribute(k1_precompute,
                             cudaFuncAttributeMaxDynamicSharedMemorySize, K1_SMEM);
        attr_set = true;
    }

    k1_precompute<<<INPUT_DIM / 128, 128, K1_SMEM>>>(emb, w1);         // 384 blocks
    k2_forward<<<BATCH / 16, 256>>>(indices, b1, w2, b2, w3, b3, out); // 1024 blocks
}

// round 15
// speedup vs baseline: 1.1683x; 1.0715x over previous
#include <cuda_runtime.h>
#include <cuda_fp16.h>
#include <cstdint>

// ---------------------------------------------------------------------------
// NNUE: out[b] = tanh(relu(relu((sum_f emb[idx[f,b]]) @ w1^T + b1) @ w2^T + b2) @ w3^T + b3)
//
// K1: g_tbl = emb @ w1^T via mma.sync m16n8k16 fp16 single-term, 128 rows/CTA.
//     NEW: two-chunk-ahead register prefetch (deeper DRAM pipeline).
// K2: warp-coalesced gather (1 LDG.32 = 2 fp16 rows). NEW: idx pairs via one
//     broadcast LDS.64; layer 2 via smem h1 broadcast instead of 64 SHFLs.
// ---------------------------------------------------------------------------

#define FULLMASK 0xffffffffu

constexpr int INPUT_DIM = 49152;
constexpr int EMB_DIM   = 256;
constexpr int BATCH     = 16384;

__device__ __half g_tbl[INPUT_DIM * 32];

__device__ __forceinline__ uint32_t smem_u32(const void* p) {
    uint32_t a;
    asm("{ .reg .u64 t; cvta.to.shared.u64 t, %1; cvt.u32.u64 %0, t; }" : "=r"(a) : "l"(p));
    return a;
}
__device__ __forceinline__ void ldmat_x4(uint32_t r[4], uint32_t addr) {
    asm volatile("ldmatrix.sync.aligned.m8n8.x4.shared.b16 {%0,%1,%2,%3}, [%4];"
                 : "=r"(r[0]), "=r"(r[1]), "=r"(r[2]), "=r"(r[3]) : "r"(addr));
}
__device__ __forceinline__ void mma_f16(float d[4], const uint32_t a[4],
                                        uint32_t b0, uint32_t b1) {
    asm volatile("mma.sync.aligned.m16n8k16.row.col.f32.f16.f16.f32 "
                 "{%0,%1,%2,%3}, {%4,%5,%6,%7}, {%8,%9}, {%0,%1,%2,%3};"
                 : "+f"(d[0]), "+f"(d[1]), "+f"(d[2]), "+f"(d[3])
                 : "r"(a[0]), "r"(a[1]), "r"(a[2]), "r"(a[3]), "r"(b0), "r"(b1));
}
__device__ __forceinline__ uint32_t cvt2h(float x, float y) {
    __half2 h = __float22half2_rn(make_float2(x, y));
    return *(uint32_t*)&h;
}

// ---------------------------------------------------------------------------
// Kernel 1.  CTA: 128 threads = 4 warps; 128 rows; grid 384.
// K in 8 chunks of 32; A double-buffered with TWO-chunk register prefetch.
// ---------------------------------------------------------------------------
constexpr int A_STRIDE = 80;
constexpr int B_STRIDE = 528;
constexpr int SZ_A = 128 * A_STRIDE;                  // 10240
constexpr int SZ_B = 32 * B_STRIDE;                   // 16896
constexpr int K1_SMEM = 2 * SZ_A + SZ_B;              // 37376

__global__ __launch_bounds__(128)
void k1_precompute(const float* __restrict__ emb, const float* __restrict__ w1) {
    extern __shared__ __align__(16) char dsm[];
    char* sA0 = dsm;
    char* sA1 = dsm + SZ_A;
    char* sB  = dsm + 2 * SZ_A;

    const int tid  = threadIdx.x;
    const int wid  = tid >> 5;
    const int lane = tid & 31;
    const int rowBase = blockIdx.x * 128;

    // ---- Prologue: convert w1 (32x256) to fp16 ----
    {
        const float4* src = (const float4*)w1;
        for (int i = tid; i < 2048; i += 128) {
            const float4 v = src[i];
            const int n = i >> 6;
            const int k = (i & 63) * 4;
            *(uint2*)(sB + n * B_STRIDE + k * 2) =
                make_uint2(cvt2h(v.x, v.y), cvt2h(v.z, v.w));
        }
    }

    const int gRow = tid >> 3;
    const int gSeg = tid & 7;

    // ---- Stage chunk 0 -> buf0; prefetch chunk 1 -> regs ----
#pragma unroll
    for (int p = 0; p < 8; p++) {
        const int row = p * 16 + gRow;
        const float4 v = *(const float4*)&emb[(size_t)(rowBase + row) * EMB_DIM + gSeg * 4];
        *(uint2*)(sA0 + row * A_STRIDE + gSeg * 8) =
            make_uint2(cvt2h(v.x, v.y), cvt2h(v.z, v.w));
    }
    float4 pre[8];
#pragma unroll
    for (int p = 0; p < 8; p++)
        pre[p] = *(const float4*)&emb[(size_t)(rowBase + p * 16 + gRow) * EMB_DIM
                                      + 32 + gSeg * 4];
    __syncthreads();

    const uint32_t aOff = (uint32_t)((wid * 32 + (lane & 15)) * A_STRIDE + (lane >> 4) * 16);
    const int bN0 = (lane & 7) + ((lane >> 4) & 1) * 8;
    const uint32_t bKoff = (uint32_t)(((lane >> 3) & 1) * 16);
    const uint32_t bBase0 = smem_u32(sB) + (uint32_t)(bN0 * B_STRIDE) + bKoff;
    const uint32_t bBase1 = bBase0 + 16 * B_STRIDE;
    const uint32_t aB0 = smem_u32(sA0) + aOff;
    const uint32_t aB1 = smem_u32(sA1) + aOff;

    float d[2][4][4];
#pragma unroll
    for (int mt = 0; mt < 2; mt++)
#pragma unroll
        for (int nt = 0; nt < 4; nt++)
#pragma unroll
            for (int r = 0; r < 4; r++) d[mt][nt][r] = 0.0f;

#pragma unroll 1
    for (int c = 0; c < 8; ++c) {
        // Commit chunk c+1 (held in regs) into the buffer last read at c-1.
        if (c < 7) {
            char* dst = ((c + 1) & 1) ? sA1 : sA0;
#pragma unroll
            for (int p = 0; p < 8; p++) {
                const int row = p * 16 + gRow;
                *(uint2*)(dst + row * A_STRIDE + gSeg * 8) =
                    make_uint2(cvt2h(pre[p].x, pre[p].y), cvt2h(pre[p].z, pre[p].w));
            }
        }
        // Issue LDG for chunk c+2 (two chunks ahead of consumption).
        if (c < 6) {
#pragma unroll
            for (int p = 0; p < 8; p++)
                pre[p] = *(const float4*)&emb[(size_t)(rowBase + p * 16 + gRow) * EMB_DIM
                                              + (c + 2) * 32 + gSeg * 4];
        }

        const uint32_t aBase = (c & 1) ? aB1 : aB0;
#pragma unroll
        for (int ks = 0; ks < 2; ++ks) {
            const uint32_t ak = (uint32_t)(ks * 32);
            const uint32_t bk = (uint32_t)(c * 64 + ks * 32);
            uint32_t aH[2][4];
            ldmat_x4(aH[0], aBase + ak);
            ldmat_x4(aH[1], aBase + ak + 16 * A_STRIDE);
            uint32_t b01[4], b23[4];
            ldmat_x4(b01, bBase0 + bk);
            ldmat_x4(b23, bBase1 + bk);

#pragma unroll
            for (int mt = 0; mt < 2; mt++) {
                mma_f16(d[mt][0], aH[mt], b01[0], b01[1]);
                mma_f16(d[mt][1], aH[mt], b01[2], b01[3]);
                mma_f16(d[mt][2], aH[mt], b23[0], b23[1]);
                mma_f16(d[mt][3], aH[mt], b23[2], b23[3]);
            }
        }
        if (c < 7) __syncthreads();
    }

    const int g = lane >> 2;
    const int cp = (lane & 3) * 2;
#pragma unroll
    for (int mt = 0; mt < 2; mt++) {
        const int r0 = rowBase + wid * 32 + mt * 16 + g;
#pragma unroll
        for (int nt = 0; nt < 4; nt++) {
            const int col = nt * 8 + cp;
            *(__half2*)&g_tbl[(size_t)r0 * 32 + col] =
                __float22half2_rn(make_float2(d[mt][nt][0], d[mt][nt][1]));
            *(__half2*)&g_tbl[(size_t)(r0 + 8) * 32 + col] =
                __float22half2_rn(make_float2(d[mt][nt][2], d[mt][nt][3]));
        }
    }
}

// ---------------------------------------------------------------------------
// Kernel 2: 16 elems/block, 256 threads = 8 warps, grid 1024.
// Warp = 2 elems. Gather: pair p: lanes 0-15 row idx[2p], 16-31 row idx[2p+1],
//   lane loads one half2; idx pair fetched as ONE broadcast LDS.64.
// Layer 2: h1 published to smem (warp-private rows, __syncwarp only), read
//   back as float4 broadcasts; w2 row register-resident. No shfl MLP.
// ---------------------------------------------------------------------------
__global__ __launch_bounds__(256)
void k2_forward(const int* __restrict__ indices,
                const float* __restrict__ b1,
                const float* __restrict__ w2,
                const float* __restrict__ b2,
                const float* __restrict__ w3,
                const float* __restrict__ b3,
                float* __restrict__ out) {
    __shared__ __align__(16) float w2s[32 * 36];
    __shared__ float w3s[32];
    __shared__ float b1s[32];
    __shared__ __align__(8)  int   idx_s[16][34];   // int2-aligned rows
    __shared__ __align__(16) float h1s[16][36];     // float4-aligned rows

    const int tid = threadIdx.x;
    const int b0 = blockIdx.x * 16;

    for (int t = tid; t < 1024; t += 256)
        w2s[(t >> 5) * 36 + (t & 31)] = w2[t];
    if (tid < 32) { w3s[tid] = w3[tid]; b1s[tid] = b1[tid]; }
    for (int t = tid; t < 512; t += 256) {
        const int f = t >> 4, e = t & 15;
        idx_s[e][f] = indices[f * BATCH + b0 + e];     // coalesced 64B runs
    }
    __syncthreads();

    const int lane = tid & 31;
    const int half = lane >> 4;          // 0: even-index rows, 1: odd
    const int l16  = lane & 15;          // col pair 2*l16, 2*l16+1
    const int e0 = (tid >> 5) * 2;

    const char* gt = (const char*)g_tbl;
    const uint32_t colOff = (uint32_t)(l16 * 4);

    // ---- Gather both elems (idx pairs via broadcast LDS.64) ----
    const int2* ia2 = (const int2*)idx_s[e0];
    const int2* ib2 = (const int2*)idx_s[e0 + 1];
    float2 accA = make_float2(0.f, 0.f);
    float2 accB = make_float2(0.f, 0.f);
#pragma unroll
    for (int p = 0; p < 16; ++p) {
        const int2 iA = ia2[p];                      // one broadcast LDS.64
        const int2 iB = ib2[p];
        const int idA = half ? iA.y : iA.x;
        const int idB = half ? iB.y : iB.x;
        const __half2 va = *(const __half2*)(gt + ((size_t)idA << 6) + colOff);
        const __half2 vb = *(const __half2*)(gt + ((size_t)idB << 6) + colOff);
        const float2 fa = __half22float2(va);
        const float2 fb = __half22float2(vb);
        accA.x += fa.x; accA.y += fa.y;
        accB.x += fb.x; accB.y += fb.y;
    }
    accA.x += __shfl_xor_sync(FULLMASK, accA.x, 16);
    accA.y += __shfl_xor_sync(FULLMASK, accA.y, 16);
    accB.x += __shfl_xor_sync(FULLMASK, accB.x, 16);
    accB.y += __shfl_xor_sync(FULLMASK, accB.y, 16);

    const float2 b1p = make_float2(b1s[2 * l16], b1s[2 * l16 + 1]);
    const float2 h1a = make_float2(fmaxf(accA.x + b1p.x, 0.f), fmaxf(accA.y + b1p.y, 0.f));
    const float2 h1b = make_float2(fmaxf(accB.x + b1p.x, 0.f), fmaxf(accB.y + b1p.y, 0.f));

    // Publish h1: lanes 0-15 write elem A's pair, lanes 16-31 elem B's.
    const float2 myh1 = half ? h1b : h1a;
    *(float2*)&h1s[e0 + half][2 * l16] = myh1;
    __syncwarp();

    // ---- Layer 2: w2 row in regs, h1 via float4 broadcast LDS ----
    float4 wrow[8];
#pragma unroll
    for (int i = 0; i < 8; i++)
        wrow[i] = *(const float4*)&w2s[lane * 36 + i * 4];
    const float* wr = (const float*)wrow;

    float h2a = b2[lane], h2b = h2a;
#pragma unroll
    for (int k4 = 0; k4 < 8; ++k4) {
        const float4 ha = *(const float4*)&h1s[e0][k4 * 4];
        const float4 hb = *(const float4*)&h1s[e0 + 1][k4 * 4];
        h2a = fmaf(ha.x, wr[4 * k4 + 0], h2a);
        h2a = fmaf(ha.y, wr[4 * k4 + 1], h2a);
        h2a = fmaf(ha.z, wr[4 * k4 + 2], h2a);
        h2a = fmaf(ha.w, wr[4 * k4 + 3], h2a);
        h2b = fmaf(hb.x, wr[4 * k4 + 0], h2b);
        h2b = fmaf(hb.y, wr[4 * k4 + 1], h2b);
        h2b = fmaf(hb.z, wr[4 * k4 + 2], h2b);
        h2b = fmaf(hb.w, wr[4 * k4 + 3], h2b);
    }
    h2a = fmaxf(h2a, 0.0f);
    h2b = fmaxf(h2b, 0.0f);

    // ---- Layer 3 ----
    float pa = h2a * w3s[lane];
    float pb = h2b * w3s[lane];
#pragma unroll
    for (int off = 16; off; off >>= 1) {
        pa += __shfl_xor_sync(FULLMASK, pa, off);
        pb += __shfl_xor_sync(FULLMASK, pb, off);
    }

    const float r = (lane & 1) ? pb : pa;
    if (lane < 2)
        out[b0 + e0 + lane] = tanhf(r + b3[0]);
}

// ---------------------------------------------------------------------------
extern "C" void kernel_launch(void* const* d_in, const int* in_sizes, int n_in,
                              void* d_out, int out_size) {
    const int*   indices = (const int*)  d_in[0];
    const float* emb     = (const float*)d_in[1];
    const float* w1      = (const float*)d_in[2];
    const float* b1      = (const float*)d_in[3];
    const float* w2      = (const float*)d_in[4];
    const float* b2      = (const float*)d_in[5];
    const float* w3      = (const float*)d_in[6];
    const float* b3      = (const float*)d_in[7];
    float* out = (float*)d_out;

    static bool attr_set = false;
    if (!attr_set) {
        cudaFuncSetAttribute(k1_precompute,
                             cudaFuncAttributeMaxDynamicSharedMemorySize, K1_SMEM);
        attr_set = true;
    }

    k1_precompute<<<INPUT_DIM / 128, 128, K1_SMEM>>>(emb, w1);         // 384 blocks
    k2_forward<<<BATCH / 16, 256>>>(indices, b1, w2, b2, w3, b3, out); // 1024 blocks
}